// round 17
// baseline (speedup 1.0000x reference)
#include <cuda_runtime.h>

// Depth-4 path signature, C=10, L=512. ONE launch, role-split grid:
//   bid in [0, 2B)   : scan role  (VERBATIM R12 scan; chunk c = bid&1)
//   bid in [2B, 4B)  : combine role (VERBATIM R12 combine; gated by flags)
// All 128 scan CTAs land in wave 1 (first 148 bids -> distinct SMs), so the
// flag-wait is deadlock-free. Combine CTA (b,h) proceeds as soon as batch
// b's two scan CTAs finish -> overlaps the scan retire-spread and removes
// the second kernel launch.

#define SIG_C 10
#define SIG_L 512
#define SIG_NSTEP 511
#define SIG_OUT 11110
#define SIG_MAXB 128
#define CHUNK0 256

typedef unsigned long long u64;

// per chunk partial: [0,110) L1|L2, [110,1110) L3, [1110,11110) L4 transposed
__device__ __align__(16) float g_part[SIG_MAXB * 2 * SIG_OUT];
// per-waiter flags: g_flag[b*4 + c*2 + h]; scan (b,c) sets h=0,1; combine
// (b,h) waits+resets (b,0,h) and (b,1,h). zero-init; self-resetting.
__device__ int g_flag[SIG_MAXB * 4];

__device__ __forceinline__ u64 ffma2(u64 a, u64 b, u64 c) {
    u64 d; asm("fma.rn.f32x2 %0, %1, %2, %3;" : "=l"(d) : "l"(a), "l"(b), "l"(c)); return d;
}
__device__ __forceinline__ u64 fmul2(u64 a, u64 b) {
    u64 d; asm("mul.rn.f32x2 %0, %1, %2;" : "=l"(d) : "l"(a), "l"(b)); return d;
}
__device__ __forceinline__ u64 fadd2(u64 a, u64 b) {
    u64 d; asm("add.rn.f32x2 %0, %1, %2;" : "=l"(d) : "l"(a), "l"(b)); return d;
}
__device__ __forceinline__ u64 pack2(float lo, float hi) {
    u64 d; asm("mov.b64 %0, {%1, %2};" : "=l"(d) : "f"(lo), "f"(hi)); return d;
}
__device__ __forceinline__ void unpack2(u64 a, float& lo, float& hi) {
    asm("mov.b64 {%0, %1}, %2;" : "=f"(lo), "=f"(hi) : "l"(a));
}

__global__ __launch_bounds__(512, 1)
void sig_mega_kernel(const float* __restrict__ path, float* __restrict__ out) {
    // scan-role smem
    __shared__ __align__(16) float dxs[CHUNK0 * 12];
    // combine-role smem
    __shared__ __align__(16) float As1[10], As2[100];
    __shared__ __align__(16) float Bs1d[16];
    __shared__ __align__(16) float Bs2[100];
    __shared__ __align__(16) float Bs3[1000];
    __shared__ __align__(16) float stage[5610];

    const int twoB = (int)gridDim.x >> 1;   // 2*B
    const int bid = blockIdx.x;
    const int tid = threadIdx.x;

    if (bid < twoB) {
        // ================= SCAN ROLE (R12 verbatim + flag release) =========
        const int b = bid >> 1;
        const int c = bid & 1;
        const int start = c ? CHUNK0 : 0;
        const int n = c ? (SIG_NSTEP - CHUNK0) : CHUNK0;   // 255 : 256
        const float* prow = path + (size_t)b * SIG_L * SIG_C + (size_t)start * SIG_C;

        for (int i = tid; i < n * SIG_C; i += 512) {
            int t = i / SIG_C;
            int cc = i - t * SIG_C;
            dxs[t * 12 + cc] = prow[(t + 1) * SIG_C + cc] - prow[t * SIG_C + cc];
        }
        __syncthreads();

        const bool active = (tid < 500);
        const int i1 = (tid / 100) % 5;
        const int i2 = (tid / 10) % 10;
        const int i3 = tid % 10;

        const u64 c1_2  = pack2(0.5f, 0.5f);
        const u64 c1_6  = pack2(1.0f / 6.0f, 1.0f / 6.0f);
        const u64 c1_24 = pack2(1.0f / 24.0f, 1.0f / 24.0f);

        u64 l1v2 = 0, l2v2 = 0, l3_2 = 0;
        u64 l4lo[5], l4hi[5];
#pragma unroll
        for (int j = 0; j < 5; ++j) { l4lo[j] = 0; l4hi[j] = 0; }

        if (active) {
            {
                float Bv = dxs[i2], Cv = dxs[i3];
                u64 A2 = pack2(dxs[i1], dxs[i1 + 5]);
                float d23 = Bv * Cv;
                u64 d23_2 = pack2(d23, d23);
                u64 B2 = pack2(Bv, Bv);
                l1v2 = A2;
                l2v2 = fmul2(fmul2(A2, B2), c1_2);
                l3_2 = fmul2(fmul2(A2, d23_2), c1_6);
                u64 c4 = fmul2(l3_2, pack2(0.25f, 0.25f));
                float clo, chi; unpack2(c4, clo, chi);
                u64 clo2 = pack2(clo, clo), chi2 = pack2(chi, chi);
                ulonglong2 va = *reinterpret_cast<const ulonglong2*>(dxs);
                ulonglong2 vb = *reinterpret_cast<const ulonglong2*>(dxs + 4);
                u64 vc = *reinterpret_cast<const u64*>(dxs + 8);
                l4lo[0] = fmul2(clo2, va.x); l4hi[0] = fmul2(chi2, va.x);
                l4lo[1] = fmul2(clo2, va.y); l4hi[1] = fmul2(chi2, va.y);
                l4lo[2] = fmul2(clo2, vb.x); l4hi[2] = fmul2(chi2, vb.x);
                l4lo[3] = fmul2(clo2, vb.y); l4hi[3] = fmul2(chi2, vb.y);
                l4lo[4] = fmul2(clo2, vc);   l4hi[4] = fmul2(chi2, vc);
            }

            const float* q1 = dxs + i1 + 12;
            const float* q2 = dxs + i2 + 12;
            const float* q3 = dxs + i3 + 12;
            const char*  qv = reinterpret_cast<const char*>(dxs) + 48;

#pragma unroll 4
            for (int t = 1; t < n; ++t) {
                float A_lo = *q1;
                float A_hi = q1[5];
                float Bv = *q2;
                float Cv = *q3;
                ulonglong2 va = *reinterpret_cast<const ulonglong2*>(qv);
                ulonglong2 vb = *reinterpret_cast<const ulonglong2*>(qv + 16);
                u64 vc = *reinterpret_cast<const u64*>(qv + 32);
                q1 += 12; q2 += 12; q3 += 12; qv += 48;

                float d23 = Bv * Cv;
                u64 A2 = pack2(A_lo, A_hi);
                u64 d23_2 = pack2(d23, d23);
                u64 C2 = pack2(Cv, Cv);
                u64 B2 = pack2(Bv, Bv);
                u64 t1 = fmul2(A2, d23_2);
                u64 uu = fmul2(l2v2, C2);
                u64 vv = fmul2(l1v2, d23_2);
                u64 coef = ffma2(c1_24, t1, ffma2(c1_2, uu, ffma2(c1_6, vv, l3_2)));
                l3_2 = ffma2(c1_6, t1, ffma2(c1_2, vv, fadd2(l3_2, uu)));
                l2v2 = ffma2(ffma2(c1_2, A2, l1v2), B2, l2v2);
                l1v2 = fadd2(l1v2, A2);

                float clo, chi; unpack2(coef, clo, chi);
                u64 clo2 = pack2(clo, clo), chi2 = pack2(chi, chi);
                l4lo[0] = ffma2(clo2, va.x, l4lo[0]); l4hi[0] = ffma2(chi2, va.x, l4hi[0]);
                l4lo[1] = ffma2(clo2, va.y, l4lo[1]); l4hi[1] = ffma2(chi2, va.y, l4hi[1]);
                l4lo[2] = ffma2(clo2, vb.x, l4lo[2]); l4hi[2] = ffma2(chi2, vb.x, l4hi[2]);
                l4lo[3] = ffma2(clo2, vb.y, l4lo[3]); l4hi[3] = ffma2(chi2, vb.y, l4hi[3]);
                l4lo[4] = ffma2(clo2, vc,   l4lo[4]); l4hi[4] = ffma2(chi2, vc,   l4hi[4]);
            }
        }

        float* dst = g_part + ((size_t)b * 2 + c) * SIG_OUT;
        float lo, hi;
        if (active) {
            if (i2 == 0 && i3 == 0) {
                unpack2(l1v2, lo, hi);
                dst[i1] = lo; dst[i1 + 5] = hi;
            }
            if (i3 == 0) {
                unpack2(l2v2, lo, hi);
                dst[10 + i1 * 10 + i2] = lo;
                dst[10 + (i1 + 5) * 10 + i2] = hi;
            }
            unpack2(l3_2, lo, hi);
            dst[110 + tid] = lo;
            dst[110 + tid + 500] = hi;
            u64* d4 = reinterpret_cast<u64*>(dst + 1110);
#pragma unroll
            for (int j = 0; j < 5; ++j) {
                d4[j * 1000 + tid]       = l4lo[j];
                d4[j * 1000 + tid + 500] = l4hi[j];
            }
        }
        __threadfence();
        __syncthreads();
        if (tid == 0) {
            asm volatile("st.release.gpu.global.b32 [%0], %1;"
                         :: "l"(g_flag + b * 4 + c * 2 + 0), "r"(1) : "memory");
            asm volatile("st.release.gpu.global.b32 [%0], %1;"
                         :: "l"(g_flag + b * 4 + c * 2 + 1), "r"(1) : "memory");
        }
        return;
    }

    // ================= COMBINE ROLE (R12 verbatim + flag gate) =============
    const int r = bid - twoB;
    const int b = r >> 1;
    const int h = r & 1;          // p-half

    if (tid == 0) {
        unsigned f;
        do {
            asm volatile("ld.acquire.gpu.global.b32 %0, [%1];"
                         : "=r"(f) : "l"(g_flag + b * 4 + 0 + h) : "memory");
        } while (f == 0);
        asm volatile("st.relaxed.gpu.global.b32 [%0], %1;"
                     :: "l"(g_flag + b * 4 + 0 + h), "r"(0) : "memory");
        do {
            asm volatile("ld.acquire.gpu.global.b32 %0, [%1];"
                         : "=r"(f) : "l"(g_flag + b * 4 + 2 + h) : "memory");
        } while (f == 0);
        asm volatile("st.relaxed.gpu.global.b32 [%0], %1;"
                     :: "l"(g_flag + b * 4 + 2 + h), "r"(0) : "memory");
    }
    __syncthreads();

    const float* a  = g_part + (size_t)(2 * b) * SIG_OUT;
    const float* bb = g_part + (size_t)(2 * b + 1) * SIG_OUT;

    for (int i = tid; i < 1000; i += 512) Bs3[i] = bb[110 + i];
    if (tid < 100) { As2[tid] = a[10 + tid]; Bs2[tid] = bb[10 + tid]; }
    if (tid < 16) Bs1d[tid] = (tid < 10) ? bb[tid] : 0.0f;
    if (tid >= 16 && tid < 26) As1[tid - 16] = a[tid - 16];
    __syncthreads();

    if (tid < 500) {
        const int p = h * 500 + tid;
        const int i1 = p / 100;
        const int i2 = (p / 10) % 10;
        const int i3 = p % 10;

        const u64* A4 = reinterpret_cast<const u64*>(a + 1110);
        const u64* B4 = reinterpret_cast<const u64*>(bb + 1110);
        u64 a4[5], b4[5];
#pragma unroll
        for (int j = 0; j < 5; ++j) a4[j] = A4[j * 1000 + p];
#pragma unroll
        for (int j = 0; j < 5; ++j) b4[j] = B4[j * 1000 + p];
        float a3 = a[110 + p];

        float a1 = As1[i1];
        float a2 = As2[i1 * 10 + i2];

        stage[110 + tid] = a3 + Bs3[p] + a2 * Bs1d[i3] + a1 * Bs2[i2 * 10 + i3];

        const u64* B1q = reinterpret_cast<const u64*>(Bs1d);
        const u64* B2q = reinterpret_cast<const u64*>(Bs2 + i3 * 10);
        const u64* B3q = reinterpret_cast<const u64*>(Bs3 + i2 * 100 + i3 * 10);
        u64 a1_2 = pack2(a1, a1);
        u64 a2_2 = pack2(a2, a2);
        u64 a3_2 = pack2(a3, a3);
        u64* s4 = reinterpret_cast<u64*>(stage + 610) + (size_t)tid * 5;
#pragma unroll
        for (int j = 0; j < 5; ++j) {
            u64 s = fadd2(a4[j], b4[j]);
            s = ffma2(a3_2, B1q[j], s);
            s = ffma2(a2_2, B2q[j], s);
            s = ffma2(a1_2, B3q[j], s);
            s4[j] = s;
        }
    }
    if (h == 0 && tid < 110) {
        if (tid < 10) {
            stage[tid] = As1[tid] + Bs1d[tid];
        } else {
            int m = tid - 10;
            stage[tid] = As2[m] + Bs2[m] + As1[m / 10] * Bs1d[m % 10];
        }
    }
    __syncthreads();

    float* ob = out + (size_t)b * SIG_OUT;
    if (h == 0) {
        const u64* sp = reinterpret_cast<const u64*>(stage);
        u64* op = reinterpret_cast<u64*>(ob);
        for (int i = tid; i < 305; i += 512) op[i] = sp[i];
        const u64* sp4 = reinterpret_cast<const u64*>(stage + 610);
        u64* op4 = reinterpret_cast<u64*>(ob + 1110);
        for (int i = tid; i < 2500; i += 512) op4[i] = sp4[i];
    } else {
        const u64* sp = reinterpret_cast<const u64*>(stage + 110);
        u64* op = reinterpret_cast<u64*>(ob + 610);
        for (int i = tid; i < 250; i += 512) op[i] = sp[i];
        const u64* sp4 = reinterpret_cast<const u64*>(stage + 610);
        u64* op4 = reinterpret_cast<u64*>(ob + 6110);
        for (int i = tid; i < 2500; i += 512) op4[i] = sp4[i];
    }
}

extern "C" void kernel_launch(void* const* d_in, const int* in_sizes, int n_in,
                              void* d_out, int out_size) {
    const float* path = (const float*)d_in[0];
    float* out = (float*)d_out;
    int B = in_sizes[0] / (SIG_L * SIG_C);
    if (B > SIG_MAXB) B = SIG_MAXB;
    sig_mega_kernel<<<B * 4, 512>>>(path, out);
}